// round 17
// baseline (speedup 1.0000x reference)
#include <cuda_runtime.h>
#include <cuda_bf16.h>
#include <cuda_fp16.h>
#include <cstdint>

// Problem constants (fixed by the dataset)
#define NN     50000
#define DD     256
#define TWO_D  512
#define EE     320000

// ---------------------------------------------------------------------------
// Scratch (static device arrays; no allocation allowed)
// ---------------------------------------------------------------------------
__device__ __half g_ABh[(size_t)NN * TWO_D];     // per-node A'|B in fp16
__device__ __half g_zf[(size_t)NN * DD];         // z in fp16, row-major [n][k]
__device__ __half g_wf[(size_t)TWO_D * DD];      // W in fp16, row-major [j][k]
__device__ int g_idx_is64;

// ---------------------------------------------------------------------------
// Fused prep kernel: z->fp16, W->fp16 (gathered layout), dtype detect.
// 8-float units (2x float4 load -> 1x uint4 store); 4 units per iteration
// -> 8 loads in flight per thread.
// ---------------------------------------------------------------------------
#define ZT8 (NN * 32)        // z 8-float units: 1,600,000
#define WT8 (TWO_D * 32)     // W 8-float units: 16,384

__device__ __forceinline__ uint4 cvt8(float4 v0, float4 v1) {
    __half2 a = __floats2half2_rn(v0.x, v0.y);
    __half2 b = __floats2half2_rn(v0.z, v0.w);
    __half2 c = __floats2half2_rn(v1.x, v1.y);
    __half2 d = __floats2half2_rn(v1.z, v1.w);
    uint4 o;
    memcpy(&o.x, &a, 4); memcpy(&o.y, &b, 4);
    memcpy(&o.z, &c, 4); memcpy(&o.w, &d, 4);
    return o;
}

__device__ __forceinline__ void convert_unit(int i, const float* z, const float* w1) {
    if (i < ZT8) {
        float4 v0 = ((const float4*)z)[2 * i];
        float4 v1 = ((const float4*)z)[2 * i + 1];
        ((uint4*)g_zf)[i] = cvt8(v0, v1);
    } else {
        int i8 = i - ZT8;
        int j  = i8 >> 5;            // 0..511
        int k  = (i8 & 31) << 3;     // 0..248 step 8
        const float* src = (j < DD) ? (w1 + (size_t)j * TWO_D + k)
                                    : (w1 + (size_t)(j - DD) * TWO_D + DD + k);
        float4 v0 = ((const float4*)src)[0];
        float4 v1 = ((const float4*)src)[1];
        ((uint4*)g_wf)[i8] = cvt8(v0, v1);
    }
}

__global__ void convert_all_kernel(const float* __restrict__ z,
                                   const float* __restrict__ w1,
                                   const int* __restrict__ ei_words) {
    const int stride = gridDim.x * blockDim.x;
    const int total  = ZT8 + WT8;
    for (int i = blockIdx.x * blockDim.x + threadIdx.x; i < total; i += 4 * stride) {
        convert_unit(i, z, w1);
        if (i + stride     < total) convert_unit(i + stride, z, w1);
        if (i + 2 * stride < total) convert_unit(i + 2 * stride, z, w1);
        if (i + 3 * stride < total) convert_unit(i + 3 * stride, z, w1);
    }
    // Inline dtype detect (int64 -> odd 32-bit words all zero for idx < 2^31)
    if (blockIdx.x == 0 && threadIdx.x < 32) {
        int found = 0;
        for (int i = threadIdx.x; i < 1024; i += 32) {
            int pos = 2 * (i * (EE / 1024)) + 1;
            if (ei_words[pos] != 0) found = 1;
        }
        unsigned any = __any_sync(0xFFFFFFFFu, found);
        if (threadIdx.x == 0) g_idx_is64 = any ? 0 : 1;
    }
}

// ---------------------------------------------------------------------------
// mma.sync helpers (sm_80+, target-independent)
// ---------------------------------------------------------------------------
__device__ __forceinline__ uint32_t smem_u32(const void* p) {
    uint32_t a;
    asm("{ .reg .u64 t; cvta.to.shared.u64 t, %1; cvt.u32.u64 %0, t; }" : "=r"(a) : "l"(p));
    return a;
}
__device__ __forceinline__ void ldm4(uint32_t* r, uint32_t addr) {
    asm volatile("ldmatrix.sync.aligned.m8n8.x4.shared.b16 {%0,%1,%2,%3}, [%4];"
                 : "=r"(r[0]), "=r"(r[1]), "=r"(r[2]), "=r"(r[3]) : "r"(addr));
}
__device__ __forceinline__ void mma16816(float* c, const uint32_t* a, uint32_t b0, uint32_t b1) {
    asm volatile("mma.sync.aligned.m16n8k16.row.col.f32.f16.f16.f32 "
                 "{%0,%1,%2,%3}, {%4,%5,%6,%7}, {%8,%9}, {%0,%1,%2,%3};"
                 : "+f"(c[0]), "+f"(c[1]), "+f"(c[2]), "+f"(c[3])
                 : "r"(a[0]), "r"(a[1]), "r"(a[2]), "r"(a[3]), "r"(b0), "r"(b1));
}
__device__ __forceinline__ void cp16(uint32_t dst, const void* src) {
    asm volatile("cp.async.cg.shared.global [%0], [%1], 16;" :: "r"(dst), "l"(src));
}

__device__ __forceinline__ uint32_t tile_off(int row, int c) {
    return row * 128 + ((c ^ (row & 7)) << 4);
}
__device__ __forceinline__ uint32_t ldm_addr(uint32_t base, int m, int c8, int lane) {
    int g = lane >> 3;
    int row = m + (lane & 7) + ((g & 1) << 3);
    int c = c8 + (g >> 1);
    return base + tile_off(row, c);
}

// ---------------------------------------------------------------------------
// Node GEMM: g_ABh[50000,512] = fp16(z @ W^T (+ b1 cols<256))
// Grid 391x4, CTA tile 128x128. Superchunk = K 64. Stage 32KB, 3-stage ring.
// 8 warps, warp tile 64x32. Single-pass fp16 MMA, fp32 accumulate.
// Register double-buffered ldmatrix fragments; SMEM-staged coalesced epilogue.
// ---------------------------------------------------------------------------
#define STAGE_STRIDE 32768
#define SM_GEMM_TOTAL 98304
#define EPAD 272                     // epilogue smem row stride (bytes)

__global__ __launch_bounds__(256, 2)
void node_gemm_mma(const float* __restrict__ b1) {
    extern __shared__ __align__(128) char smem[];
    const uint32_t sbase = smem_u32(smem);
    const int tid  = threadIdx.x;
    const int lane = tid & 31;
    const int wid  = tid >> 5;
    const int wm   = wid >> 2;
    const int wn   = wid & 3;
    const int m0   = blockIdx.x * 128;
    const int j0   = blockIdx.y * 128;

    const uint32_t rbase = (uint32_t)(tid >> 3);
    const uint32_t dst0  = rbase * 128u +
        ((((uint32_t)tid & 7u) ^ (rbase & 7u)) << 4);
    const char* zb2 = (const char*)g_zf + (((uint32_t)tid & 7u) << 4);
    const char* wb2 = (const char*)g_wf + (((uint32_t)tid & 7u) << 4);

    const char* asrc[4];
    #pragma unroll
    for (int i = 0; i < 4; i++) {
        uint32_t gr = (uint32_t)m0 + rbase + 32u * i;
        if (gr >= NN) gr = NN - 1;
        asrc[i] = zb2 + (size_t)gr * 512u;
    }
    const char* bsrc[4];
    #pragma unroll
    for (int i = 0; i < 4; i++)
        bsrc[i] = wb2 + (size_t)(j0 + (int)(rbase + 32u * i)) * 512u;

    auto issue = [&](int sc, int s) {
        uint32_t stb = sbase + (uint32_t)s * STAGE_STRIDE;
        uint32_t off = (uint32_t)sc * 128u;
        #pragma unroll
        for (int i = 0; i < 4; i++)
            cp16(stb + dst0 + i * 4096u, asrc[i] + off);
        #pragma unroll
        for (int i = 0; i < 4; i++)
            cp16(stb + 16384u + dst0 + i * 4096u, bsrc[i] + off);
        asm volatile("cp.async.commit_group;" ::: "memory");
    };

    issue(0, 0);
    issue(1, 1);
    issue(2, 2);

    float acc[16][4];
    #pragma unroll
    for (int i = 0; i < 16; i++)
        #pragma unroll
        for (int q = 0; q < 4; q++) acc[i][q] = 0.f;

    // Double-buffered fragments
    uint32_t ah[2][4][4], bh[2][2][4];

    #pragma unroll 1
    for (int sc = 0; sc < 4; sc++) {
        if (sc == 0)      asm volatile("cp.async.wait_group 2;" ::: "memory");
        else if (sc == 1) asm volatile("cp.async.wait_group 2;" ::: "memory");
        else if (sc == 2) asm volatile("cp.async.wait_group 1;" ::: "memory");
        else              asm volatile("cp.async.wait_group 0;" ::: "memory");
        __syncthreads();

        const uint32_t stb = sbase + (uint32_t)(sc % 3) * STAGE_STRIDE;
        const uint32_t Ab = stb;
        const uint32_t Bb = stb + 16384u;

        // Prime buffer 0 with kk=0 fragments
        #pragma unroll
        for (int q = 0; q < 2; q++)
            ldm4(bh[0][q], ldm_addr(Bb, wn * 32 + q * 16, 0, lane));
        #pragma unroll
        for (int mt = 0; mt < 4; mt++)
            ldm4(ah[0][mt], ldm_addr(Ab, wm * 64 + mt * 16, 0, lane));

        #pragma unroll
        for (int kk = 0; kk < 4; kk++) {
            const int cur = kk & 1;
            const int nxt = cur ^ 1;
            if (kk < 3) {
                const int c8n = 2 * (kk + 1);
                #pragma unroll
                for (int q = 0; q < 2; q++)
                    ldm4(bh[nxt][q], ldm_addr(Bb, wn * 32 + q * 16, c8n, lane));
                #pragma unroll
                for (int mt = 0; mt < 4; mt++)
                    ldm4(ah[nxt][mt], ldm_addr(Ab, wm * 64 + mt * 16, c8n, lane));
            }
            #pragma unroll
            for (int mt = 0; mt < 4; mt++)
                #pragma unroll
                for (int nt = 0; nt < 4; nt++) {
                    uint32_t h0 = bh[cur][nt >> 1][nt & 1];
                    uint32_t h1 = bh[cur][nt >> 1][(nt & 1) + 2];
                    mma16816(acc[mt * 4 + nt], ah[cur][mt], h0, h1);
                }
        }

        if (sc == 0) {
            __syncthreads();
            issue(3, 0);
        }
    }

    // ---- Epilogue: stage through SMEM for fully-coalesced 16B stores ----
    __syncthreads();     // all warps done reading SMEM stages
    const bool has_bias = (j0 < DD);
    #pragma unroll
    for (int nt = 0; nt < 4; nt++) {
        int colh = wn * 32 + nt * 8 + (lane & 3) * 2;   // local col (halves)
        float bv0 = 0.f, bv1 = 0.f;
        if (has_bias) {
            bv0 = __ldg(&b1[j0 + colh]);
            bv1 = __ldg(&b1[j0 + colh + 1]);
        }
        #pragma unroll
        for (int mt = 0; mt < 4; mt++) {
            float* cc = acc[mt * 4 + nt];
            int r0 = wm * 64 + mt * 16 + (lane >> 2);
            *(__half2*)(smem + r0 * EPAD + colh * 2) =
                __floats2half2_rn(cc[0] + bv0, cc[1] + bv1);
            *(__half2*)(smem + (r0 + 8) * EPAD + colh * 2) =
                __floats2half2_rn(cc[2] + bv0, cc[3] + bv1);
        }
    }
    __syncthreads();
    {
        int row  = tid >> 1;
        int half = tid & 1;
        int gr   = m0 + row;
        if (gr < NN) {
            const char* src = smem + row * EPAD + half * 128;
            __half* dst = g_ABh + (size_t)gr * TWO_D + j0 + half * 64;
            #pragma unroll
            for (int i = 0; i < 8; i++) {
                uint4 v = *(const uint4*)(src + i * 16);
                *(uint4*)(dst + i * 8) = v;
            }
        }
    }
}

// ---------------------------------------------------------------------------
// Edge kernel: 8 edges per warp iteration, all 16 row-loads up front (MLP 16).
//   out[e] = sum_d w2[d] * relu(A'[src][d] + B[dst][d]) + b2
// add+relu in half2, dot in fp32.
// ---------------------------------------------------------------------------
__device__ __forceinline__ float dot8h(uint4 av, uint4 cv, float4 wA, float4 wB) {
    const __half2* a = (const __half2*)&av;
    const __half2* c = (const __half2*)&cv;
    const __half2 z2 = __float2half2_rn(0.f);
    __half2 h0 = __hmax2(__hadd2(a[0], c[0]), z2);
    __half2 h1 = __hmax2(__hadd2(a[1], c[1]), z2);
    __half2 h2 = __hmax2(__hadd2(a[2], c[2]), z2);
    __half2 h3 = __hmax2(__hadd2(a[3], c[3]), z2);
    float2 f0 = __half22float2(h0);
    float2 f1 = __half22float2(h1);
    float2 f2 = __half22float2(h2);
    float2 f3 = __half22float2(h3);
    float acc;
    acc  = f0.x * wA.x;
    acc  = fmaf(f0.y, wA.y, acc);
    acc  = fmaf(f1.x, wA.z, acc);
    acc  = fmaf(f1.y, wA.w, acc);
    acc  = fmaf(f2.x, wB.x, acc);
    acc  = fmaf(f2.y, wB.y, acc);
    acc  = fmaf(f3.x, wB.z, acc);
    acc  = fmaf(f3.y, wB.w, acc);
    return acc;
}

template <bool IS64>
__device__ __forceinline__ void edge_loop(const void* ei_raw,
                                          const float* w2,
                                          const float* b2,
                                          float* out,
                                          int lane, int warp, int nwarps) {
    const float4 wA = __ldg((const float4*)w2 + 2 * lane);
    const float4 wB = __ldg((const float4*)w2 + 2 * lane + 1);
    const float  b2v = __ldg(b2);

    const int*       ei32 = (const int*)ei_raw;
    const long long* ei64 = (const long long*)ei_raw;

    const int q = lane >> 3;
    const bool writer = (lane & 7) == 0;

    for (int e0 = warp * 8; e0 < EE; e0 += nwarps * 8) {
        int s[8], d[8];
        #pragma unroll
        for (int u = 0; u < 8; u++) {
            if (IS64) { s[u] = (int)ei64[e0 + u]; d[u] = (int)ei64[EE + e0 + u]; }
            else      { s[u] = ei32[e0 + u];      d[u] = ei32[EE + e0 + u]; }
        }

        uint4 av[8], cv[8];
        #pragma unroll
        for (int u = 0; u < 8; u++) {
            av[u] = __ldg((const uint4*)(g_ABh + (size_t)s[u] * TWO_D) + lane);
            cv[u] = __ldg((const uint4*)(g_ABh + (size_t)d[u] * TWO_D + DD) + lane);
        }

        float r[8];
        #pragma unroll
        for (int u = 0; u < 8; u++)
            r[u] = dot8h(av[u], cv[u], wA, wB);

        #pragma unroll
        for (int u = 0; u < 8; u++)
            r[u] += __shfl_xor_sync(0xFFFFFFFFu, r[u], 16);
        #pragma unroll
        for (int u = 0; u < 8; u++)
            r[u] += __shfl_xor_sync(0xFFFFFFFFu, r[u], 8);

        float v0 = (q == 0) ? r[0] : (q == 1) ? r[1] : (q == 2) ? r[2] : r[3];
        float v1 = (q == 0) ? r[4] : (q == 1) ? r[5] : (q == 2) ? r[6] : r[7];
        #pragma unroll
        for (int o = 4; o > 0; o >>= 1) {
            v0 += __shfl_xor_sync(0xFFFFFFFFu, v0, o);
            v1 += __shfl_xor_sync(0xFFFFFFFFu, v1, o);
        }

        if (writer) {
            out[e0 + q]     = v0 + b2v;
            out[e0 + 4 + q] = v1 + b2v;
        }
    }
}

__global__ __launch_bounds__(256)
void edge_kernel(const void* __restrict__ ei_raw,
                 const float* __restrict__ w2,
                 const float* __restrict__ b2,
                 float* __restrict__ out) {
    const int lane   = threadIdx.x & 31;
    const int warp   = (blockIdx.x * blockDim.x + threadIdx.x) >> 5;
    const int nwarps = (gridDim.x * blockDim.x) >> 5;

    if (g_idx_is64)
        edge_loop<true>(ei_raw, w2, b2, out, lane, warp, nwarps);
    else
        edge_loop<false>(ei_raw, w2, b2, out, lane, warp, nwarps);
}

// ---------------------------------------------------------------------------
extern "C" void kernel_launch(void* const* d_in, const int* in_sizes, int n_in,
                              void* d_out, int out_size) {
    const float* z  = (const float*)d_in[0];
    const void*  ei = d_in[1];
    const float* w1 = (const float*)d_in[2];
    const float* b1 = (const float*)d_in[3];
    const float* w2 = (const float*)d_in[4];
    const float* b2 = (const float*)d_in[5];
    float*       out = (float*)d_out;

    cudaFuncSetAttribute(node_gemm_mma, cudaFuncAttributeMaxDynamicSharedMemorySize,
                         SM_GEMM_TOTAL);

    convert_all_kernel<<<1024, 256>>>(z, w1, (const int*)ei);

    dim3 ggrid((NN + 127) / 128, 4);   // 391 x 4
    node_gemm_mma<<<ggrid, 256, SM_GEMM_TOTAL>>>(b1);

    edge_kernel<<<1184, 256>>>(ei, w2, b2, out);
}